// round 16
// baseline (speedup 1.0000x reference)
#include <cuda_runtime.h>
#include <cuda_fp16.h>
#include <math_constants.h>
#include <cstdint>

#define B_  2
#define S_  2048
#define DM  1024
#define DK  64
#define H_  16
#define BH  (B_ * H_)
#define ROWS (B_ * S_)          // 4096

// ---------------------------------------------------------------------------
// Scratch (allocation-free: device globals)
// ---------------------------------------------------------------------------
__device__ __half g_x16[ROWS * DM];
__device__ __half g_wq[DM * DM], g_wk[DM * DM], g_wv[DM * DM];
__device__ __half g_wo[DM * DM];
__device__ __half g_q[BH * S_ * DK], g_k[BH * S_ * DK], g_v[BH * S_ * DK];
__device__ __half g_cxh[ROWS * DM], g_cxl[ROWS * DM];

// Q pre-scale: (1/sqrt(64)) * log2(e)  -> softmax computed in base-2
#define Q_ALPHA 0.18033688011112042f

// ---------------------------------------------------------------------------
// Helpers
// ---------------------------------------------------------------------------
__device__ __forceinline__ uint32_t smem_to_u32(const void* p) {
    uint32_t a;
    asm("{ .reg .u64 t; cvta.to.shared.u64 t, %1; cvt.u32.u64 %0, t; }"
        : "=r"(a) : "l"(p));
    return a;
}
__device__ __forceinline__ void mma16816h(float* c, const uint32_t* a, const uint32_t* b) {
    asm volatile("mma.sync.aligned.m16n8k16.row.col.f32.f16.f16.f32 "
        "{%0,%1,%2,%3}, {%4,%5,%6,%7}, {%8,%9}, {%0,%1,%2,%3};"
        : "+f"(c[0]), "+f"(c[1]), "+f"(c[2]), "+f"(c[3])
        : "r"(a[0]), "r"(a[1]), "r"(a[2]), "r"(a[3]), "r"(b[0]), "r"(b[1]));
}
__device__ __forceinline__ void ldsm_x4(uint32_t* r, uint32_t a) {
    asm volatile("ldmatrix.sync.aligned.m8n8.x4.shared.b16 {%0,%1,%2,%3}, [%4];"
        : "=r"(r[0]), "=r"(r[1]), "=r"(r[2]), "=r"(r[3]) : "r"(a));
}
__device__ __forceinline__ void ldsm_x4_t(uint32_t* r, uint32_t a) {
    asm volatile("ldmatrix.sync.aligned.m8n8.x4.trans.shared.b16 {%0,%1,%2,%3}, [%4];"
        : "=r"(r[0]), "=r"(r[1]), "=r"(r[2]), "=r"(r[3]) : "r"(a));
}
__device__ __forceinline__ void cp16(uint32_t d, const void* s) {
    asm volatile("cp.async.cg.shared.global [%0], [%1], 16;" :: "r"(d), "l"(s));
}
#define CP_COMMIT asm volatile("cp.async.commit_group;" ::: "memory")
#define CP_WAIT2  asm volatile("cp.async.wait_group 2;" ::: "memory")
#define CP_WAIT1  asm volatile("cp.async.wait_group 1;" ::: "memory")
#define CP_WAIT0  asm volatile("cp.async.wait_group 0;" ::: "memory")

__device__ __forceinline__ uint32_t packh(float lo, float hi) {
    uint32_t r;
    asm("cvt.rn.f16x2.f32 %0, %1, %2;" : "=r"(r) : "f"(hi), "f"(lo));
    return r;
}

// ---------------------------------------------------------------------------
// Fused prep kernel (R14)
// ---------------------------------------------------------------------------
__global__ __launch_bounds__(256) void prep_all(
    const float* __restrict__ x,
    const float* __restrict__ Wq, const float* __restrict__ Wk,
    const float* __restrict__ Wv, const float* __restrict__ Wo)
{
    __shared__ float tile[32][33];
    const int bid = blockIdx.x;
    const int t = threadIdx.x;

    if (bid < 512) {
        const int n4 = (ROWS * DM) / 4;
        for (int i = bid * 256 + t; i < n4; i += 512 * 256) {
            float4 v = ((const float4*)x)[i];
            uint2 o;
            o.x = packh(v.x, v.y);
            o.y = packh(v.z, v.w);
            ((uint2*)g_x16)[i] = o;
        }
        return;
    }

    const int tx = t & 31, ty = t >> 5;

    if (bid < 3584) {
        int which = (bid - 512) >> 10;
        int idx = (bid - 512) & 1023;
        const float* W = (which == 0) ? Wq : (which == 1) ? Wk : Wv;
        __half* dst    = (which == 0) ? g_wq : (which == 1) ? g_wk : g_wv;
        int k0 = (idx & 31) * 32;
        int c0 = ((idx >> 5) & 1) * 32;
        int h  = idx >> 6;
        const float* src = W + (size_t)h * DM * DK;
        #pragma unroll
        for (int i = 0; i < 32; i += 8)
            tile[ty + i][tx] = src[(size_t)(k0 + ty + i) * DK + c0 + tx];
        __syncthreads();
        #pragma unroll
        for (int i = 0; i < 32; i += 8) {
            int n = h * 64 + c0 + ty + i;
            dst[(size_t)n * DM + k0 + tx] = __float2half_rn(tile[tx][ty + i]);
        }
    } else {
        int idx = bid - 3584;
        int k0 = (idx & 31) * 32;
        int n0 = (idx >> 5) * 32;
        #pragma unroll
        for (int i = 0; i < 32; i += 8)
            tile[ty + i][tx] = Wo[(size_t)(k0 + ty + i) * DM + n0 + tx];
        __syncthreads();
        #pragma unroll
        for (int i = 0; i < 32; i += 8) {
            int n = n0 + ty + i;
            g_wo[(size_t)n * DM + k0 + tx] = __float2half_rn(tile[tx][ty + i]);
        }
    }
}

// ---------------------------------------------------------------------------
// GEMM geometry: BK = 64, R14 config (256 threads, 8 warps, 64x32 warp tile)
// ---------------------------------------------------------------------------
#define GBK 64
#define GROW 144
#define GPLANE (128 * GROW)             // 18432 B

// ---------------------------------------------------------------------------
// QKV projection GEMM: fp16 single product, fused Q/K/V via z. BK=64.
// ---------------------------------------------------------------------------
#define QSTAGE (2 * GPLANE)             // 36864 : x, W
#define QKV_SMEM (2 * QSTAGE)           // 73728

__global__ __launch_bounds__(256) void gemm_qkv(const __half* __restrict__ x16)
{
    extern __shared__ char smem[];
    const uint32_t sb = smem_to_u32(smem);
    const int t = threadIdx.x, w = t >> 5, ln = t & 31;
    const int wm = (w & 1) * 64, wn = (w >> 1) * 32;
    const int row0 = blockIdx.x * 128, col0 = blockIdx.y * 128;
    const int z = blockIdx.z;

    const __half* W = (z == 0) ? g_wq : (z == 1) ? g_wk : g_wv;
    __half* out     = (z == 0) ? g_q  : (z == 1) ? g_k  : g_v;
    const float alpha = (z == 0) ? Q_ALPHA : 1.0f;

    const __half* src[2] = { x16 + (size_t)row0 * DM, W + (size_t)col0 * DM };

    float c[4][4][4] = {};

    {
        #pragma unroll
        for (int pi = 0; pi < 2; pi++)
            #pragma unroll
            for (int j = 0; j < 4; j++) {
                int pos = t + j * 256, row = pos >> 3, seg = pos & 7;
                cp16(sb + pi * GPLANE + row * GROW + seg * 16,
                     src[pi] + (size_t)row * DM + seg * 8);
            }
        CP_COMMIT;
    }

    for (int kc = 0; kc < DM / GBK; kc++) {
        if (kc + 1 < DM / GBK) {
            int k0 = (kc + 1) * GBK;
            uint32_t stn = sb + ((kc + 1) & 1) * QSTAGE;
            #pragma unroll
            for (int pi = 0; pi < 2; pi++)
                #pragma unroll
                for (int j = 0; j < 4; j++) {
                    int pos = t + j * 256, row = pos >> 3, seg = pos & 7;
                    cp16(stn + pi * GPLANE + row * GROW + seg * 16,
                         src[pi] + (size_t)row * DM + k0 + seg * 8);
                }
            CP_COMMIT;
            CP_WAIT1;
        } else {
            CP_WAIT0;
        }
        __syncthreads();
        uint32_t st = sb + (kc & 1) * QSTAGE;

        #pragma unroll
        for (int ks = 0; ks < 4; ks++) {
            uint32_t bh[4][2];
            #pragma unroll
            for (int np = 0; np < 2; np++) {
                uint32_t baddr = st + GPLANE
                    + (wn + np * 16 + ((ln >> 4) & 1) * 8 + (ln & 7)) * GROW
                    + ks * 32 + ((ln >> 3) & 1) * 16;
                uint32_t r[4];
                ldsm_x4(r, baddr);
                bh[2*np][0] = r[0]; bh[2*np][1] = r[1];
                bh[2*np+1][0] = r[2]; bh[2*np+1][1] = r[3];
            }
            #pragma unroll
            for (int mi = 0; mi < 4; mi++) {
                uint32_t aaddr = st + (wm + mi * 16 + (ln & 15)) * GROW
                               + ks * 32 + (ln >> 4) * 16;
                uint32_t ah[4];
                ldsm_x4(ah, aaddr);
                #pragma unroll
                for (int ni = 0; ni < 4; ni++)
                    mma16816h(c[mi][ni], ah, bh[ni]);
            }
        }
        __syncthreads();
    }

    #pragma unroll
    for (int mi = 0; mi < 4; mi++) {
        int r = row0 + wm + mi * 16 + (ln >> 2);
        #pragma unroll
        for (int ni = 0; ni < 4; ni++) {
            int cc = col0 + wn + ni * 8 + 2 * (ln & 3);
            int h = cc >> 6, d = cc & 63;
            #pragma unroll
            for (int rr = 0; rr < 2; rr++) {
                int row = r + rr * 8;
                int b = row >> 11, s = row & (S_ - 1);
                size_t idx = ((size_t)((b << 4) + h) * S_ + s) * DK + d;
                *(uint32_t*)&out[idx] = packh(c[mi][ni][2*rr] * alpha,
                                              c[mi][ni][2*rr+1] * alpha);
            }
        }
    }
}

// ---------------------------------------------------------------------------
// Output projection GEMM: fp16 2-product, fp32 out. BK=64, R14 config.
// ---------------------------------------------------------------------------
#define OSTAGE (3 * GPLANE)             // 55296 : cxh, cxl, Wo
#define OUT_SMEM (2 * OSTAGE)           // 110592

__global__ __launch_bounds__(256) void gemm_out(float* __restrict__ outf)
{
    extern __shared__ char smem[];
    const uint32_t sb = smem_to_u32(smem);
    const int t = threadIdx.x, w = t >> 5, ln = t & 31;
    const int wm = (w & 1) * 64, wn = (w >> 1) * 32;
    const int row0 = blockIdx.x * 128, col0 = blockIdx.y * 128;

    const __half* src[3] = {
        g_cxh + (size_t)row0 * DM, g_cxl + (size_t)row0 * DM,
        g_wo + (size_t)col0 * DM };

    float c[4][4][4] = {};

    {
        #pragma unroll
        for (int pi = 0; pi < 3; pi++)
            #pragma unroll
            for (int j = 0; j < 4; j++) {
                int pos = t + j * 256, row = pos >> 3, seg = pos & 7;
                cp16(sb + pi * GPLANE + row * GROW + seg * 16,
                     src[pi] + (size_t)row * DM + seg * 8);
            }
        CP_COMMIT;
    }

    for (int kc = 0; kc < DM / GBK; kc++) {
        if (kc + 1 < DM / GBK) {
            int k0 = (kc + 1) * GBK;
            uint32_t stn = sb + ((kc + 1) & 1) * OSTAGE;
            #pragma unroll
            for (int pi = 0; pi < 3; pi++)
                #pragma unroll
                for (int j = 0; j < 4; j++) {
                    int pos = t + j * 256, row = pos >> 3, seg = pos & 7;
                    cp16(stn + pi * GPLANE + row * GROW + seg * 16,
                         src[pi] + (size_t)row * DM + k0 + seg * 8);
                }
            CP_COMMIT;
            CP_WAIT1;
        } else {
            CP_WAIT0;
        }
        __syncthreads();
        uint32_t st = sb + (kc & 1) * OSTAGE;

        #pragma unroll
        for (int ks = 0; ks < 4; ks++) {
            uint32_t bh[4][2];
            #pragma unroll
            for (int np = 0; np < 2; np++) {
                uint32_t baddr = st + 2 * GPLANE
                    + (wn + np * 16 + ((ln >> 4) & 1) * 8 + (ln & 7)) * GROW
                    + ks * 32 + ((ln >> 3) & 1) * 16;
                uint32_t r[4];
                ldsm_x4(r, baddr);
                bh[2*np][0] = r[0]; bh[2*np][1] = r[1];
                bh[2*np+1][0] = r[2]; bh[2*np+1][1] = r[3];
            }
            #pragma unroll
            for (int mi = 0; mi < 4; mi++) {
                uint32_t aaddr = st + (wm + mi * 16 + (ln & 15)) * GROW
                               + ks * 32 + (ln >> 4) * 16;
                uint32_t ah[4], al[4];
                ldsm_x4(ah, aaddr);
                ldsm_x4(al, aaddr + GPLANE);
                #pragma unroll
                for (int ni = 0; ni < 4; ni++)
                    mma16816h(c[mi][ni], ah, bh[ni]);
                #pragma unroll
                for (int ni = 0; ni < 4; ni++)
                    mma16816h(c[mi][ni], al, bh[ni]);
            }
        }
        __syncthreads();
    }

    #pragma unroll
    for (int mi = 0; mi < 4; mi++) {
        int r = row0 + wm + mi * 16 + (ln >> 2);
        #pragma unroll
        for (int ni = 0; ni < 4; ni++) {
            int cc = col0 + wn + ni * 8 + 2 * (ln & 3);
            *(float2*)&outf[(size_t)r * DM + cc] =
                make_float2(c[mi][ni][0], c[mi][ni][1]);
            *(float2*)&outf[(size_t)(r + 8) * DM + cc] =
                make_float2(c[mi][ni][2], c[mi][ni][3]);
        }
    }
}

// ---------------------------------------------------------------------------
// FP16 flash attention: 3-stage cp.async K/V ring (bit-identical math),
// software-pipelined scores, warp-uniform rescale skip.
// ---------------------------------------------------------------------------
#define AT_ROWSZ 144
#define AT_PLANE (128 * AT_ROWSZ)        // 18432 B
#define AT_STAGE (2 * AT_PLANE)          // 36864 : K, V
#define ATT_SMEM (3 * AT_STAGE)          // 110592 (3-stage ring)
#define NIT (S_ / 128)                   // 16

__device__ __forceinline__ void attn_scores(
    uint32_t st, int half, int ln, const uint32_t qh[4][8], float sc[2][4][4])
{
    #pragma unroll
    for (int mi = 0; mi < 2; mi++)
        #pragma unroll
        for (int nj = 0; nj < 4; nj++)
            #pragma unroll
            for (int e = 0; e < 4; e++)
                sc[mi][nj][e] = 0.f;
    #pragma unroll
    for (int ks = 0; ks < 4; ks++) {
        #pragma unroll
        for (int np = 0; np < 2; np++) {
            uint32_t baddr = st
                + (half * 32 + np * 16 + ((ln >> 4) & 1) * 8 + (ln & 7)) * AT_ROWSZ
                + ks * 32 + ((ln >> 3) & 1) * 16;
            uint32_t rh[4];
            ldsm_x4(rh, baddr);
            uint32_t b0[2] = { rh[0], rh[1] }, b1[2] = { rh[2], rh[3] };
            #pragma unroll
            for (int mi = 0; mi < 2; mi++) {
                mma16816h(sc[mi][2*np],   qh[ks] + mi*4, b0);
                mma16816h(sc[mi][2*np+1], qh[ks] + mi*4, b1);
            }
        }
    }
}

__global__ __launch_bounds__(128, 2) void attn_mma()
{
    extern __shared__ char smem[];
    const uint32_t sb = smem_to_u32(smem);
    const int t = threadIdx.x, w = t >> 5, ln = t & 31;
    const int bh = blockIdx.y, q0 = blockIdx.x * 128;
    const size_t hbase = (size_t)bh * S_ * DK;

    uint32_t qh[4][8];
    #pragma unroll
    for (int mi = 0; mi < 2; mi++) {
        int r = q0 + w * 32 + mi * 16 + (ln >> 2);
        int cb = 2 * (ln & 3);
        #pragma unroll
        for (int ks = 0; ks < 4; ks++) {
            int c0 = ks * 16 + cb;
            qh[ks][mi*4+0] = *(const uint32_t*)&g_q[hbase + (size_t)r * DK + c0];
            qh[ks][mi*4+1] = *(const uint32_t*)&g_q[hbase + (size_t)(r + 8) * DK + c0];
            qh[ks][mi*4+2] = *(const uint32_t*)&g_q[hbase + (size_t)r * DK + c0 + 8];
            qh[ks][mi*4+3] = *(const uint32_t*)&g_q[hbase + (size_t)(r + 8) * DK + c0 + 8];
        }
    }

    float ctx[2][8][4] = {};
    float mx[2][2], ls[2][2];
    #pragma unroll
    for (int i = 0; i < 2; i++) {
        mx[i][0] = -CUDART_INF_F; mx[i][1] = -CUDART_INF_F;
        ls[i][0] = 0.f; ls[i][1] = 0.f;
    }

    const __half* gsrc[2] = { g_k + hbase, g_v + hbase };
    const int krow = t >> 3, kseg = t & 7;

    // prologue: issue stages 0 and 1
    #pragma unroll
    for (int s = 0; s < 2; s++) {
        #pragma unroll
        for (int pi = 0; pi < 2; pi++)
            #pragma unroll
            for (int j = 0; j < 8; j++) {
                int row = krow + j * 16;
                cp16(sb + s * AT_STAGE + pi * AT_PLANE + row * AT_ROWSZ + kseg * 16,
                     gsrc[pi] + (size_t)(s * 128 + row) * DK + kseg * 8);
            }
        CP_COMMIT;
    }

    float scbuf[2][2][4][4];
    int s_cur = 0;   // ring slot for iteration `it`

    for (int it = 0; it < NIT; it++) {
        if (it + 2 < NIT) {
            int s_nxt = s_cur + 2; if (s_nxt >= 3) s_nxt -= 3;
            uint32_t stn = sb + s_nxt * AT_STAGE;
            #pragma unroll
            for (int pi = 0; pi < 2; pi++)
                #pragma unroll
                for (int j = 0; j < 8; j++) {
                    int row = krow + j * 16;
                    cp16(stn + pi * AT_PLANE + row * AT_ROWSZ + kseg * 16,
                         gsrc[pi] + (size_t)((it + 2) * 128 + row) * DK + kseg * 8);
                }
            CP_COMMIT;
            CP_WAIT2;
        } else if (it + 1 < NIT) {
            CP_WAIT1;
        } else {
            CP_WAIT0;
        }
        __syncthreads();
        uint32_t st = sb + s_cur * AT_STAGE;

        attn_scores(st, 0, ln, qh, scbuf[0]);

        #pragma unroll
        for (int half = 0; half < 4; half++) {
            float (*sc)[4][4] = scbuf[half & 1];

            #pragma unroll
            for (int mi = 0; mi < 2; mi++) {
                float rm0 = -CUDART_INF_F, rm1 = -CUDART_INF_F;
                #pragma unroll
                for (int nj = 0; nj < 4; nj++) {
                    rm0 = fmaxf(rm0, fmaxf(sc[mi][nj][0], sc[mi][nj][1]));
                    rm1 = fmaxf(rm1, fmaxf(sc[mi][nj][2], sc[mi][nj][3]));
                }
                rm0 = fmaxf(rm0, __shfl_xor_sync(0xffffffffu, rm0, 1));
                rm0 = fmaxf(rm0, __shfl_xor_sync(0xffffffffu, rm0, 2));
                rm1 = fmaxf(rm1, __shfl_xor_sync(0xffffffffu, rm1, 1));
                rm1 = fmaxf(rm1, __shfl_xor_sync(0xffffffffu, rm1, 2));
                float mn0 = fmaxf(mx[mi][0], rm0), mn1 = fmaxf(mx[mi][1], rm1);

                float a0 = 1.0f, a1 = 1.0f;
                bool upd = (mn0 > mx[mi][0]) || (mn1 > mx[mi][1]);
                if (__any_sync(0xffffffffu, upd)) {
                    a0 = exp2f(mx[mi][0] - mn0);
                    a1 = exp2f(mx[mi][1] - mn1);
                    mx[mi][0] = mn0; mx[mi][1] = mn1;
                    #pragma unroll
                    for (int vt = 0; vt < 8; vt++) {
                        ctx[mi][vt][0] *= a0; ctx[mi][vt][1] *= a0;
                        ctx[mi][vt][2] *= a1; ctx[mi][vt][3] *= a1;
                    }
                }

                float rs0 = 0.f, rs1 = 0.f;
                #pragma unroll
                for (int nj = 0; nj < 4; nj++) {
                    sc[mi][nj][0] = exp2f(sc[mi][nj][0] - mn0);
                    sc[mi][nj][1] = exp2f(sc[mi][nj][1] - mn0);
                    sc[mi][nj][2] = exp2f(sc[mi][nj][2] - mn1);
                    sc[mi][nj][3] = exp2f(sc[mi][nj][3] - mn1);
                    rs0 += sc[mi][nj][0] + sc[mi][nj][1];
                    rs1 += sc[mi][nj][2] + sc[mi][nj][3];
                }
                rs0 += __shfl_xor_sync(0xffffffffu, rs0, 1);
                rs0 += __shfl_xor_sync(0xffffffffu, rs0, 2);
                rs1 += __shfl_xor_sync(0xffffffffu, rs1, 1);
                rs1 += __shfl_xor_sync(0xffffffffu, rs1, 2);
                ls[mi][0] = ls[mi][0] * a0 + rs0;
                ls[mi][1] = ls[mi][1] * a1 + rs1;
            }

            uint32_t ph[2][2][4];
            #pragma unroll
            for (int mi = 0; mi < 2; mi++)
                #pragma unroll
                for (int kk = 0; kk < 2; kk++)
                    #pragma unroll
                    for (int e = 0; e < 4; e++) {
                        int tile = 2 * kk + (e >> 1);
                        int o = (e & 1) * 2;
                        ph[mi][kk][e] = packh(sc[mi][tile][o], sc[mi][tile][o + 1]);
                    }

            uint32_t vf[2][4][4];
            #pragma unroll
            for (int kk = 0; kk < 2; kk++)
                #pragma unroll
                for (int vp = 0; vp < 4; vp++) {
                    uint32_t vaddr = st + AT_PLANE
                        + (half * 32 + kk * 16 + ((ln >> 3) & 1) * 8 + (ln & 7)) * AT_ROWSZ
                        + vp * 32 + ((ln >> 4) & 1) * 16;
                    ldsm_x4_t(vf[kk][vp], vaddr);
                }

            if (half < 3)
                attn_scores(st, half + 1, ln, qh, scbuf[(half + 1) & 1]);

            #pragma unroll
            for (int kk = 0; kk < 2; kk++) {
                #pragma unroll
                for (int vp = 0; vp < 4; vp++) {
                    uint32_t b0[2] = { vf[kk][vp][0], vf[kk][vp][1] };
                    uint32_t b1[2] = { vf[kk][vp][2], vf[kk][vp][3] };
                    #pragma unroll
                    for (int mi = 0; mi < 2; mi++) {
                        mma16816h(ctx[mi][2*vp],   ph[mi][kk], b0);
                        mma16816h(ctx[mi][2*vp+1], ph[mi][kk], b1);
                    }
                }
            }
        }
        __syncthreads();
        s_cur = (s_cur + 1 == 3) ? 0 : s_cur + 1;
    }

    const int b = bh >> 4, h = bh & 15;
    #pragma unroll
    for (int mi = 0; mi < 2; mi++) {
        float inv0 = 1.f / ls[mi][0], inv1 = 1.f / ls[mi][1];
        int r = q0 + w * 32 + mi * 16 + (ln >> 2);
        size_t ob0 = ((size_t)(b * S_ + r)) * DM + h * 64;
        size_t ob1 = ob0 + (size_t)8 * DM;
        #pragma unroll
        for (int vt = 0; vt < 8; vt++) {
            int cc = vt * 8 + 2 * (ln & 3);
            float v0 = ctx[mi][vt][0] * inv0, v1 = ctx[mi][vt][1] * inv0;
            float v2 = ctx[mi][vt][2] * inv1, v3 = ctx[mi][vt][3] * inv1;
            uint32_t pA = packh(v0, v1);
            uint32_t pB = packh(v2, v3);
            *(uint32_t*)&g_cxh[ob0 + cc] = pA;
            *(uint32_t*)&g_cxh[ob1 + cc] = pB;
            __half2 hA = *(__half2*)&pA, hB = *(__half2*)&pB;
            *(uint32_t*)&g_cxl[ob0 + cc] =
                packh(v0 - __half2float(__low2half(hA)),
                      v1 - __half2float(__high2half(hA)));
            *(uint32_t*)&g_cxl[ob1 + cc] =
                packh(v2 - __half2float(__low2half(hB)),
                      v3 - __half2float(__high2half(hB)));
        }
    }
}

// ---------------------------------------------------------------------------
// Launch. Input order per metadata: x, Wk, Wq, Wv, Wo
// ---------------------------------------------------------------------------
extern "C" void kernel_launch(void* const* d_in, const int* in_sizes, int n_in,
                              void* d_out, int out_size)
{
    const float* x  = (const float*)d_in[0];
    const float* Wk = (const float*)d_in[1];
    const float* Wq = (const float*)d_in[2];
    const float* Wv = (const float*)d_in[3];
    const float* Wo = (const float*)d_in[4];
    float* out = (float*)d_out;

    cudaFuncSetAttribute(gemm_qkv,
                         cudaFuncAttributeMaxDynamicSharedMemorySize, QKV_SMEM);
    cudaFuncSetAttribute(gemm_out,
                         cudaFuncAttributeMaxDynamicSharedMemorySize, OUT_SMEM);
    cudaFuncSetAttribute(attn_mma,
                         cudaFuncAttributeMaxDynamicSharedMemorySize, ATT_SMEM);

    __half *x16;
    cudaGetSymbolAddress((void**)&x16, g_x16);

    prep_all<<<4608, 256>>>(x, Wq, Wk, Wv, Wo);

    gemm_qkv<<<dim3(32, 8, 3), 256, QKV_SMEM>>>(x16);

    attn_mma<<<dim3(S_ / 128, BH), 128, ATT_SMEM>>>();

    gemm_out<<<dim3(32, 8), 256, OUT_SMEM>>>(out);
}

// round 17
// speedup vs baseline: 1.0072x; 1.0072x over previous
#include <cuda_runtime.h>
#include <cuda_fp16.h>
#include <math_constants.h>
#include <cstdint>

#define B_  2
#define S_  2048
#define DM  1024
#define DK  64
#define H_  16
#define BH  (B_ * H_)
#define ROWS (B_ * S_)          // 4096

// ---------------------------------------------------------------------------
// Scratch (allocation-free: device globals)
// ---------------------------------------------------------------------------
__device__ __half g_x16[ROWS * DM];
__device__ __half g_wq[DM * DM], g_wk[DM * DM], g_wv[DM * DM];
__device__ __half g_wo[DM * DM];
__device__ __half g_q[BH * S_ * DK], g_k[BH * S_ * DK], g_v[BH * S_ * DK];
__device__ __half g_cxh[ROWS * DM], g_cxl[ROWS * DM];

// Q pre-scale: (1/sqrt(64)) * log2(e)  -> softmax computed in base-2
#define Q_ALPHA 0.18033688011112042f

// ---------------------------------------------------------------------------
// Helpers
// ---------------------------------------------------------------------------
__device__ __forceinline__ uint32_t smem_to_u32(const void* p) {
    uint32_t a;
    asm("{ .reg .u64 t; cvta.to.shared.u64 t, %1; cvt.u32.u64 %0, t; }"
        : "=r"(a) : "l"(p));
    return a;
}
__device__ __forceinline__ void mma16816h(float* c, const uint32_t* a, const uint32_t* b) {
    asm volatile("mma.sync.aligned.m16n8k16.row.col.f32.f16.f16.f32 "
        "{%0,%1,%2,%3}, {%4,%5,%6,%7}, {%8,%9}, {%0,%1,%2,%3};"
        : "+f"(c[0]), "+f"(c[1]), "+f"(c[2]), "+f"(c[3])
        : "r"(a[0]), "r"(a[1]), "r"(a[2]), "r"(a[3]), "r"(b[0]), "r"(b[1]));
}
__device__ __forceinline__ void ldsm_x4(uint32_t* r, uint32_t a) {
    asm volatile("ldmatrix.sync.aligned.m8n8.x4.shared.b16 {%0,%1,%2,%3}, [%4];"
        : "=r"(r[0]), "=r"(r[1]), "=r"(r[2]), "=r"(r[3]) : "r"(a));
}
__device__ __forceinline__ void ldsm_x4_t(uint32_t* r, uint32_t a) {
    asm volatile("ldmatrix.sync.aligned.m8n8.x4.trans.shared.b16 {%0,%1,%2,%3}, [%4];"
        : "=r"(r[0]), "=r"(r[1]), "=r"(r[2]), "=r"(r[3]) : "r"(a));
}
__device__ __forceinline__ void cp16(uint32_t d, const void* s) {
    asm volatile("cp.async.cg.shared.global [%0], [%1], 16;" :: "r"(d), "l"(s));
}
#define CP_COMMIT asm volatile("cp.async.commit_group;" ::: "memory")
#define CP_WAIT1  asm volatile("cp.async.wait_group 1;" ::: "memory")
#define CP_WAIT0  asm volatile("cp.async.wait_group 0;" ::: "memory")

__device__ __forceinline__ uint32_t packh(float lo, float hi) {
    uint32_t r;
    asm("cvt.rn.f16x2.f32 %0, %1, %2;" : "=r"(r) : "f"(hi), "f"(lo));
    return r;
}

// ---------------------------------------------------------------------------
// Prep kernel: x (vectorized) + Wq/Wk/Wv per-head transposes. Wo moved into
// gemm_qkv's grid (z=3) where it overlaps with GEMM work.
//   blocks [0,512)     : x  (grid-stride float4)
//   blocks [512,3584)  : Wq/Wk/Wv
// ---------------------------------------------------------------------------
__global__ __launch_bounds__(256) void prep_all(
    const float* __restrict__ x,
    const float* __restrict__ Wq, const float* __restrict__ Wk,
    const float* __restrict__ Wv)
{
    __shared__ float tile[32][33];
    const int bid = blockIdx.x;
    const int t = threadIdx.x;

    if (bid < 512) {
        const int n4 = (ROWS * DM) / 4;
        for (int i = bid * 256 + t; i < n4; i += 512 * 256) {
            float4 v = ((const float4*)x)[i];
            uint2 o;
            o.x = packh(v.x, v.y);
            o.y = packh(v.z, v.w);
            ((uint2*)g_x16)[i] = o;
        }
        return;
    }

    const int tx = t & 31, ty = t >> 5;

    int which = (bid - 512) >> 10;
    int idx = (bid - 512) & 1023;
    const float* W = (which == 0) ? Wq : (which == 1) ? Wk : Wv;
    __half* dst    = (which == 0) ? g_wq : (which == 1) ? g_wk : g_wv;
    int k0 = (idx & 31) * 32;
    int c0 = ((idx >> 5) & 1) * 32;
    int h  = idx >> 6;
    const float* src = W + (size_t)h * DM * DK;
    #pragma unroll
    for (int i = 0; i < 32; i += 8)
        tile[ty + i][tx] = src[(size_t)(k0 + ty + i) * DK + c0 + tx];
    __syncthreads();
    #pragma unroll
    for (int i = 0; i < 32; i += 8) {
        int n = h * 64 + c0 + ty + i;
        dst[(size_t)n * DM + k0 + tx] = __float2half_rn(tile[tx][ty + i]);
    }
}

// ---------------------------------------------------------------------------
// GEMM geometry: BK = 64, 256 threads, 8 warps, 64x32 warp tile (R14 config)
// ---------------------------------------------------------------------------
#define GBK 64
#define GROW 144
#define GPLANE (128 * GROW)             // 18432 B

// ---------------------------------------------------------------------------
// QKV projection GEMM + Wo-prep side work:
//   z in {0,1,2}: fp16 single-product GEMM for Q/K/V
//   z == 3      : Wo transpose fp32->fp16 (4 sub-tiles per block)
// ---------------------------------------------------------------------------
#define QSTAGE (2 * GPLANE)             // 36864 : x, W
#define QKV_SMEM (2 * QSTAGE)           // 73728

__global__ __launch_bounds__(256) void gemm_qkv(
    const __half* __restrict__ x16, const float* __restrict__ Wo)
{
    extern __shared__ char smem[];
    const int t = threadIdx.x;
    const int z = blockIdx.z;

    if (z == 3) {
        // Wo transpose: 256 blocks x 4 sub-tiles = 1024 (32x32) tiles
        float (*tile)[33] = (float(*)[33])smem;
        const int tx = t & 31, ty = t >> 5;
        int base = (blockIdx.y * 32 + blockIdx.x) * 4;
        #pragma unroll
        for (int s = 0; s < 4; s++) {
            int idx = base + s;
            int k0 = (idx & 31) * 32;
            int n0 = (idx >> 5) * 32;
            #pragma unroll
            for (int i = 0; i < 32; i += 8)
                tile[ty + i][tx] = Wo[(size_t)(k0 + ty + i) * DM + n0 + tx];
            __syncthreads();
            #pragma unroll
            for (int i = 0; i < 32; i += 8) {
                int n = n0 + ty + i;
                g_wo[(size_t)n * DM + k0 + tx] = __float2half_rn(tile[tx][ty + i]);
            }
            __syncthreads();
        }
        return;
    }

    const uint32_t sb = smem_to_u32(smem);
    const int w = t >> 5, ln = t & 31;
    const int wm = (w & 1) * 64, wn = (w >> 1) * 32;
    const int row0 = blockIdx.x * 128, col0 = blockIdx.y * 128;

    const __half* W = (z == 0) ? g_wq : (z == 1) ? g_wk : g_wv;
    __half* out     = (z == 0) ? g_q  : (z == 1) ? g_k  : g_v;
    const float alpha = (z == 0) ? Q_ALPHA : 1.0f;

    const __half* src[2] = { x16 + (size_t)row0 * DM, W + (size_t)col0 * DM };

    float c[4][4][4] = {};

    {
        #pragma unroll
        for (int pi = 0; pi < 2; pi++)
            #pragma unroll
            for (int j = 0; j < 4; j++) {
                int pos = t + j * 256, row = pos >> 3, seg = pos & 7;
                cp16(sb + pi * GPLANE + row * GROW + seg * 16,
                     src[pi] + (size_t)row * DM + seg * 8);
            }
        CP_COMMIT;
    }

    for (int kc = 0; kc < DM / GBK; kc++) {
        if (kc + 1 < DM / GBK) {
            int k0 = (kc + 1) * GBK;
            uint32_t stn = sb + ((kc + 1) & 1) * QSTAGE;
            #pragma unroll
            for (int pi = 0; pi < 2; pi++)
                #pragma unroll
                for (int j = 0; j < 4; j++) {
                    int pos = t + j * 256, row = pos >> 3, seg = pos & 7;
                    cp16(stn + pi * GPLANE + row * GROW + seg * 16,
                         src[pi] + (size_t)row * DM + k0 + seg * 8);
                }
            CP_COMMIT;
            CP_WAIT1;
        } else {
            CP_WAIT0;
        }
        __syncthreads();
        uint32_t st = sb + (kc & 1) * QSTAGE;

        #pragma unroll
        for (int ks = 0; ks < 4; ks++) {
            uint32_t bh[4][2];
            #pragma unroll
            for (int np = 0; np < 2; np++) {
                uint32_t baddr = st + GPLANE
                    + (wn + np * 16 + ((ln >> 4) & 1) * 8 + (ln & 7)) * GROW
                    + ks * 32 + ((ln >> 3) & 1) * 16;
                uint32_t r[4];
                ldsm_x4(r, baddr);
                bh[2*np][0] = r[0]; bh[2*np][1] = r[1];
                bh[2*np+1][0] = r[2]; bh[2*np+1][1] = r[3];
            }
            #pragma unroll
            for (int mi = 0; mi < 4; mi++) {
                uint32_t aaddr = st + (wm + mi * 16 + (ln & 15)) * GROW
                               + ks * 32 + (ln >> 4) * 16;
                uint32_t ah[4];
                ldsm_x4(ah, aaddr);
                #pragma unroll
                for (int ni = 0; ni < 4; ni++)
                    mma16816h(c[mi][ni], ah, bh[ni]);
            }
        }
        __syncthreads();
    }

    #pragma unroll
    for (int mi = 0; mi < 4; mi++) {
        int r = row0 + wm + mi * 16 + (ln >> 2);
        #pragma unroll
        for (int ni = 0; ni < 4; ni++) {
            int cc = col0 + wn + ni * 8 + 2 * (ln & 3);
            int h = cc >> 6, d = cc & 63;
            #pragma unroll
            for (int rr = 0; rr < 2; rr++) {
                int row = r + rr * 8;
                int b = row >> 11, s = row & (S_ - 1);
                size_t idx = ((size_t)((b << 4) + h) * S_ + s) * DK + d;
                *(uint32_t*)&out[idx] = packh(c[mi][ni][2*rr] * alpha,
                                              c[mi][ni][2*rr+1] * alpha);
            }
        }
    }
}

// ---------------------------------------------------------------------------
// Output projection GEMM: fp16 2-product, fp32 out. BK=64, R14 config.
// ---------------------------------------------------------------------------
#define OSTAGE (3 * GPLANE)             // 55296 : cxh, cxl, Wo
#define OUT_SMEM (2 * OSTAGE)           // 110592

__global__ __launch_bounds__(256) void gemm_out(float* __restrict__ outf)
{
    extern __shared__ char smem[];
    const uint32_t sb = smem_to_u32(smem);
    const int t = threadIdx.x, w = t >> 5, ln = t & 31;
    const int wm = (w & 1) * 64, wn = (w >> 1) * 32;
    const int row0 = blockIdx.x * 128, col0 = blockIdx.y * 128;

    const __half* src[3] = {
        g_cxh + (size_t)row0 * DM, g_cxl + (size_t)row0 * DM,
        g_wo + (size_t)col0 * DM };

    float c[4][4][4] = {};

    {
        #pragma unroll
        for (int pi = 0; pi < 3; pi++)
            #pragma unroll
            for (int j = 0; j < 4; j++) {
                int pos = t + j * 256, row = pos >> 3, seg = pos & 7;
                cp16(sb + pi * GPLANE + row * GROW + seg * 16,
                     src[pi] + (size_t)row * DM + seg * 8);
            }
        CP_COMMIT;
    }

    for (int kc = 0; kc < DM / GBK; kc++) {
        if (kc + 1 < DM / GBK) {
            int k0 = (kc + 1) * GBK;
            uint32_t stn = sb + ((kc + 1) & 1) * OSTAGE;
            #pragma unroll
            for (int pi = 0; pi < 3; pi++)
                #pragma unroll
                for (int j = 0; j < 4; j++) {
                    int pos = t + j * 256, row = pos >> 3, seg = pos & 7;
                    cp16(stn + pi * GPLANE + row * GROW + seg * 16,
                         src[pi] + (size_t)row * DM + k0 + seg * 8);
                }
            CP_COMMIT;
            CP_WAIT1;
        } else {
            CP_WAIT0;
        }
        __syncthreads();
        uint32_t st = sb + (kc & 1) * OSTAGE;

        #pragma unroll
        for (int ks = 0; ks < 4; ks++) {
            uint32_t bh[4][2];
            #pragma unroll
            for (int np = 0; np < 2; np++) {
                uint32_t baddr = st + 2 * GPLANE
                    + (wn + np * 16 + ((ln >> 4) & 1) * 8 + (ln & 7)) * GROW
                    + ks * 32 + ((ln >> 3) & 1) * 16;
                uint32_t r[4];
                ldsm_x4(r, baddr);
                bh[2*np][0] = r[0]; bh[2*np][1] = r[1];
                bh[2*np+1][0] = r[2]; bh[2*np+1][1] = r[3];
            }
            #pragma unroll
            for (int mi = 0; mi < 4; mi++) {
                uint32_t aaddr = st + (wm + mi * 16 + (ln & 15)) * GROW
                               + ks * 32 + (ln >> 4) * 16;
                uint32_t ah[4], al[4];
                ldsm_x4(ah, aaddr);
                ldsm_x4(al, aaddr + GPLANE);
                #pragma unroll
                for (int ni = 0; ni < 4; ni++)
                    mma16816h(c[mi][ni], ah, bh[ni]);
                #pragma unroll
                for (int ni = 0; ni < 4; ni++)
                    mma16816h(c[mi][ni], al, bh[ni]);
            }
        }
        __syncthreads();
    }

    #pragma unroll
    for (int mi = 0; mi < 4; mi++) {
        int r = row0 + wm + mi * 16 + (ln >> 2);
        #pragma unroll
        for (int ni = 0; ni < 4; ni++) {
            int cc = col0 + wn + ni * 8 + 2 * (ln & 3);
            *(float2*)&outf[(size_t)r * DM + cc] =
                make_float2(c[mi][ni][0], c[mi][ni][1]);
            *(float2*)&outf[(size_t)(r + 8) * DM + cc] =
                make_float2(c[mi][ni][2], c[mi][ni][3]);
        }
    }
}

// ---------------------------------------------------------------------------
// FP16 flash attention (R14: 2-stage pipeline, software-pipelined scores,
// warp-uniform rescale skip, hoisted V fragments)
// ---------------------------------------------------------------------------
#define AT_ROWSZ 144
#define AT_PLANE (128 * AT_ROWSZ)        // 18432 B
#define AT_STAGE (2 * AT_PLANE)          // 36864 : K, V
#define ATT_SMEM (2 * AT_STAGE)          // 73728

__device__ __forceinline__ void attn_scores(
    uint32_t st, int half, int ln, const uint32_t qh[4][8], float sc[2][4][4])
{
    #pragma unroll
    for (int mi = 0; mi < 2; mi++)
        #pragma unroll
        for (int nj = 0; nj < 4; nj++)
            #pragma unroll
            for (int e = 0; e < 4; e++)
                sc[mi][nj][e] = 0.f;
    #pragma unroll
    for (int ks = 0; ks < 4; ks++) {
        #pragma unroll
        for (int np = 0; np < 2; np++) {
            uint32_t baddr = st
                + (half * 32 + np * 16 + ((ln >> 4) & 1) * 8 + (ln & 7)) * AT_ROWSZ
                + ks * 32 + ((ln >> 3) & 1) * 16;
            uint32_t rh[4];
            ldsm_x4(rh, baddr);
            uint32_t b0[2] = { rh[0], rh[1] }, b1[2] = { rh[2], rh[3] };
            #pragma unroll
            for (int mi = 0; mi < 2; mi++) {
                mma16816h(sc[mi][2*np],   qh[ks] + mi*4, b0);
                mma16816h(sc[mi][2*np+1], qh[ks] + mi*4, b1);
            }
        }
    }
}

__global__ __launch_bounds__(128, 2) void attn_mma()
{
    extern __shared__ char smem[];
    const uint32_t sb = smem_to_u32(smem);
    const int t = threadIdx.x, w = t >> 5, ln = t & 31;
    const int bh = blockIdx.y, q0 = blockIdx.x * 128;
    const size_t hbase = (size_t)bh * S_ * DK;

    uint32_t qh[4][8];
    #pragma unroll
    for (int mi = 0; mi < 2; mi++) {
        int r = q0 + w * 32 + mi * 16 + (ln >> 2);
        int cb = 2 * (ln & 3);
        #pragma unroll
        for (int ks = 0; ks < 4; ks++) {
            int c0 = ks * 16 + cb;
            qh[ks][mi*4+0] = *(const uint32_t*)&g_q[hbase + (size_t)r * DK + c0];
            qh[ks][mi*4+1] = *(const uint32_t*)&g_q[hbase + (size_t)(r + 8) * DK + c0];
            qh[ks][mi*4+2] = *(const uint32_t*)&g_q[hbase + (size_t)r * DK + c0 + 8];
            qh[ks][mi*4+3] = *(const uint32_t*)&g_q[hbase + (size_t)(r + 8) * DK + c0 + 8];
        }
    }

    float ctx[2][8][4] = {};
    float mx[2][2], ls[2][2];
    #pragma unroll
    for (int i = 0; i < 2; i++) {
        mx[i][0] = -CUDART_INF_F; mx[i][1] = -CUDART_INF_F;
        ls[i][0] = 0.f; ls[i][1] = 0.f;
    }

    const __half* gsrc[2] = { g_k + hbase, g_v + hbase };
    const int krow = t >> 3, kseg = t & 7;

    {
        #pragma unroll
        for (int pi = 0; pi < 2; pi++)
            #pragma unroll
            for (int j = 0; j < 8; j++) {
                int row = krow + j * 16;
                cp16(sb + pi * AT_PLANE + row * AT_ROWSZ + kseg * 16,
                     gsrc[pi] + (size_t)row * DK + kseg * 8);
            }
        CP_COMMIT;
    }

    float scbuf[2][2][4][4];

    for (int it = 0; it < S_ / 128; it++) {
        if (it + 1 < S_ / 128) {
            uint32_t stn = sb + ((it + 1) & 1) * AT_STAGE;
            #pragma unroll
            for (int pi = 0; pi < 2; pi++)
                #pragma unroll
                for (int j = 0; j < 8; j++) {
                    int row = krow + j * 16;
                    cp16(stn + pi * AT_PLANE + row * AT_ROWSZ + kseg * 16,
                         gsrc[pi] + (size_t)((it + 1) * 128 + row) * DK + kseg * 8);
                }
            CP_COMMIT;
            CP_WAIT1;
        } else {
            CP_WAIT0;
        }
        __syncthreads();
        uint32_t st = sb + (it & 1) * AT_STAGE;

        attn_scores(st, 0, ln, qh, scbuf[0]);

        #pragma unroll
        for (int half = 0; half < 4; half++) {
            float (*sc)[4][4] = scbuf[half & 1];

            #pragma unroll
            for (int mi = 0; mi < 2; mi++) {
                float rm0 = -CUDART_INF_F, rm1 = -CUDART_INF_F;
                #pragma unroll
                for (int nj = 0; nj < 4; nj++) {
                    rm0 = fmaxf(rm0, fmaxf(sc[mi][nj][0], sc[mi][nj][1]));
                    rm1 = fmaxf(rm1, fmaxf(sc[mi][nj][2], sc[mi][nj][3]));
                }
                rm0 = fmaxf(rm0, __shfl_xor_sync(0xffffffffu, rm0, 1));
                rm0 = fmaxf(rm0, __shfl_xor_sync(0xffffffffu, rm0, 2));
                rm1 = fmaxf(rm1, __shfl_xor_sync(0xffffffffu, rm1, 1));
                rm1 = fmaxf(rm1, __shfl_xor_sync(0xffffffffu, rm1, 2));
                float mn0 = fmaxf(mx[mi][0], rm0), mn1 = fmaxf(mx[mi][1], rm1);

                float a0 = 1.0f, a1 = 1.0f;
                bool upd = (mn0 > mx[mi][0]) || (mn1 > mx[mi][1]);
                if (__any_sync(0xffffffffu, upd)) {
                    a0 = exp2f(mx[mi][0] - mn0);
                    a1 = exp2f(mx[mi][1] - mn1);
                    mx[mi][0] = mn0; mx[mi][1] = mn1;
                    #pragma unroll
                    for (int vt = 0; vt < 8; vt++) {
                        ctx[mi][vt][0] *= a0; ctx[mi][vt][1] *= a0;
                        ctx[mi][vt][2] *= a1; ctx[mi][vt][3] *= a1;
                    }
                }

                float rs0 = 0.f, rs1 = 0.f;
                #pragma unroll
                for (int nj = 0; nj < 4; nj++) {
                    sc[mi][nj][0] = exp2f(sc[mi][nj][0] - mn0);
                    sc[mi][nj][1] = exp2f(sc[mi][nj][1] - mn0);
                    sc[mi][nj][2] = exp2f(sc[mi][nj][2] - mn1);
                    sc[mi][nj][3] = exp2f(sc[mi][nj][3] - mn1);
                    rs0 += sc[mi][nj][0] + sc[mi][nj][1];
                    rs1 += sc[mi][nj][2] + sc[mi][nj][3];
                }
                rs0 += __shfl_xor_sync(0xffffffffu, rs0, 1);
                rs0 += __shfl_xor_sync(0xffffffffu, rs0, 2);
                rs1 += __shfl_xor_sync(0xffffffffu, rs1, 1);
                rs1 += __shfl_xor_sync(0xffffffffu, rs1, 2);
                ls[mi][0] = ls[mi][0] * a0 + rs0;
                ls[mi][1] = ls[mi][1] * a1 + rs1;
            }

            uint32_t ph[2][2][4];
            #pragma unroll
            for (int mi = 0; mi < 2; mi++)
                #pragma unroll
                for (int kk = 0; kk < 2; kk++)
                    #pragma unroll
                    for (int e = 0; e < 4; e++) {
                        int tile = 2 * kk + (e >> 1);
                        int o = (e & 1) * 2;
                        ph[mi][kk][e] = packh(sc[mi][tile][o], sc[mi][tile][o + 1]);
                    }

            uint32_t vf[2][4][4];
            #pragma unroll
            for (int kk = 0; kk < 2; kk++)
                #pragma unroll
                for (int vp = 0; vp < 4; vp++) {
                    uint32_t vaddr = st + AT_PLANE
                        + (half * 32 + kk * 16 + ((ln >> 3) & 1) * 8 + (ln & 7)) * AT_ROWSZ
                        + vp * 32 + ((ln >> 4) & 1) * 16;
                    ldsm_x4_t(vf[kk][vp], vaddr);
                }

            if (half < 3)
                attn_scores(st, half + 1, ln, qh, scbuf[(half + 1) & 1]);

            #pragma unroll
            for (int kk = 0; kk < 2; kk++) {
                #pragma unroll
                for (int vp = 0; vp < 4; vp++) {
                    uint32_t b0[2] = { vf[kk][vp][0], vf[kk][vp][1] };
                    uint32_t b1[2] = { vf[kk][vp][2], vf[kk][vp][3] };
                    #pragma unroll
                    for (int mi = 0; mi < 2; mi++) {
                        mma16816h(ctx[mi][2*vp],   ph[mi][kk], b0);
                        mma16816h(ctx[mi][2*vp+1], ph[mi][kk], b1);
                    }
                }
            }
        }
        __syncthreads();
    }

    const int b = bh >> 4, h = bh & 15;
    #pragma unroll
    for (int mi = 0; mi < 2; mi++) {
        float inv0 = 1.f / ls[mi][0], inv1 = 1.f / ls[mi][1];
        int r = q0 + w * 32 + mi * 16 + (ln >> 2);
        size_t ob0 = ((size_t)(b * S_ + r)) * DM + h * 64;
        size_t ob1 = ob0 + (size_t)8 * DM;
        #pragma unroll
        for (int vt = 0; vt < 8; vt++) {
            int cc = vt * 8 + 2 * (ln & 3);
            float v0 = ctx[mi][vt][0] * inv0, v1 = ctx[mi][vt][1] * inv0;
            float v2 = ctx[mi][vt][2] * inv1, v3 = ctx[mi][vt][3] * inv1;
            uint32_t pA = packh(v0, v1);
            uint32_t pB = packh(v2, v3);
            *(uint32_t*)&g_cxh[ob0 + cc] = pA;
            *(uint32_t*)&g_cxh[ob1 + cc] = pB;
            __half2 hA = *(__half2*)&pA, hB = *(__half2*)&pB;
            *(uint32_t*)&g_cxl[ob0 + cc] =
                packh(v0 - __half2float(__low2half(hA)),
                      v1 - __half2float(__high2half(hA)));
            *(uint32_t*)&g_cxl[ob1 + cc] =
                packh(v2 - __half2float(__low2half(hB)),
                      v3 - __half2float(__high2half(hB)));
        }
    }
}

// ---------------------------------------------------------------------------
// Launch. Input order per metadata: x, Wk, Wq, Wv, Wo
// ---------------------------------------------------------------------------
extern "C" void kernel_launch(void* const* d_in, const int* in_sizes, int n_in,
                              void* d_out, int out_size)
{
    const float* x  = (const float*)d_in[0];
    const float* Wk = (const float*)d_in[1];
    const float* Wq = (const float*)d_in[2];
    const float* Wv = (const float*)d_in[3];
    const float* Wo = (const float*)d_in[4];
    float* out = (float*)d_out;

    cudaFuncSetAttribute(gemm_qkv,
                         cudaFuncAttributeMaxDynamicSharedMemorySize, QKV_SMEM);
    cudaFuncSetAttribute(gemm_out,
                         cudaFuncAttributeMaxDynamicSharedMemorySize, OUT_SMEM);
    cudaFuncSetAttribute(attn_mma,
                         cudaFuncAttributeMaxDynamicSharedMemorySize, ATT_SMEM);

    __half *x16;
    cudaGetSymbolAddress((void**)&x16, g_x16);

    prep_all<<<3584, 256>>>(x, Wq, Wk, Wv);

    gemm_qkv<<<dim3(32, 8, 4), 256, QKV_SMEM>>>(x16, Wo);

    attn_mma<<<dim3(S_ / 128, BH), 128, ATT_SMEM>>>();

    gemm_out<<<dim3(32, 8), 256, OUT_SMEM>>>(out);
}